// round 5
// baseline (speedup 1.0000x reference)
#include <cuda_runtime.h>

typedef unsigned long long ull;

__device__ __forceinline__ ull pack2(float lo, float hi) {
    ull r; asm("mov.b64 %0, {%1, %2};" : "=l"(r) : "f"(lo), "f"(hi)); return r;
}
__device__ __forceinline__ void unpack2(ull v, float& lo, float& hi) {
    asm("mov.b64 {%0, %1}, %2;" : "=f"(lo), "=f"(hi) : "l"(v));
}
__device__ __forceinline__ void fma2(ull& d, ull a, ull b) {
    asm("fma.rn.f32x2 %0, %1, %2, %0;" : "+l"(d) : "l"(a), "l"(b));
}

#define NB 256
#define LC 400
#define LQ 50
#define DD 128
#define CH 100

// scratch (__device__ globals: allowed; no allocation)
__device__ float d_Sraw[(size_t)NB * LC * LQ];        // 20.5 MB
__device__ float d_cstatP[NB * 4 * LQ * 2];           // partial (m,s)
__device__ float d_Apart[(size_t)NB * 4 * LQ * DD];   // 26.2 MB

// ---------------- K1: S tile + row softmax (S_bar out) + column partials ----
__global__ __launch_bounds__(256)
void k1_score(const float* __restrict__ g_xc, const float* __restrict__ g_xq,
              const float* __restrict__ g_W0, const float* __restrict__ g_W1,
              const float* __restrict__ g_W2, const int* __restrict__ g_clen,
              const int* __restrict__ g_qlen, float* __restrict__ out)
{
    __shared__ __align__(16) float xqT[32 * 51];
    __shared__ __align__(16) float xcT[32 * 102];
    __shared__ __align__(16) float Ssm[CH * 51];
    __shared__ float sc[CH];
    __shared__ float sq[LQ];

    const int b = blockIdx.y, c0 = blockIdx.x * CH;
    const int t = threadIdx.x, lane = t & 31, w = t >> 5;
    const float* xcb = g_xc + (size_t)b * LC * DD;
    const float* xqb = g_xq + (size_t)b * LQ * DD;

    // s_q[q] = xq[q] . W1
    for (int q = w; q < LQ; q += 8) {
        float4 v = *(const float4*)(xqb + q * DD + lane * 4);
        float4 wv = __ldg((const float4*)g_W1 + lane);
        float p = v.x * wv.x + v.y * wv.y + v.z * wv.z + v.w * wv.w;
        #pragma unroll
        for (int o = 16; o; o >>= 1) p += __shfl_xor_sync(~0u, p, o);
        if (!lane) sq[q] = p;
    }
    if (t < CH) sc[t] = 0.f;

    ull acc[2][5];
    #pragma unroll
    for (int i = 0; i < 2; i++)
        #pragma unroll
        for (int j = 0; j < 5; j++) acc[i][j] = 0ull;
    const int ct = t / 10, qt = t - ct * 10;
    const bool act = t < 250;
    const int cb = ct * 4, qb = qt * 5;

    for (int s4 = 0; s4 < 4; s4++) {
        const int d0 = s4 * 32;
        __syncthreads();
        for (int i = t; i < LQ * 32; i += 256) {
            int q = i >> 5;  // lane == dd
            xqT[lane * 51 + q] = xqb[q * DD + d0 + lane];
        }
        float w0v = __ldg(g_W0 + d0 + lane);
        float w2v = __ldg(g_W2 + d0 + lane);
        for (int i = t; i < CH * 32; i += 256) {
            int cc = i >> 5;
            float v = xcb[(size_t)(c0 + cc) * DD + d0 + lane];
            xcT[lane * 102 + cc] = v * w2v;
            float p = v * w0v;
            #pragma unroll
            for (int o = 16; o; o >>= 1) p += __shfl_xor_sync(~0u, p, o);
            if (!lane) sc[cc] += p;
        }
        __syncthreads();
        if (act) {
            #pragma unroll 8
            for (int dd = 0; dd < 32; dd++) {
                ull a0 = *(const ull*)&xcT[dd * 102 + cb];
                ull a1 = *(const ull*)&xcT[dd * 102 + cb + 2];
                #pragma unroll
                for (int j = 0; j < 5; j++) {
                    float xv = xqT[dd * 51 + qb + j];
                    ull bb = pack2(xv, xv);
                    fma2(acc[0][j], a0, bb);
                    fma2(acc[1][j], a1, bb);
                }
            }
        }
    }
    if (act) {
        #pragma unroll
        for (int i = 0; i < 2; i++) {
            #pragma unroll
            for (int j = 0; j < 5; j++) {
                float lo, hi; unpack2(acc[i][j], lo, hi);
                int cA = cb + i * 2, q = qb + j;
                Ssm[cA * 51 + q]       = lo + sc[cA]     + sq[q];
                Ssm[(cA + 1) * 51 + q] = hi + sc[cA + 1] + sq[q];
            }
        }
    }
    __syncthreads();

    // raw S -> scratch
    float* Sraw_b = d_Sraw + ((size_t)b * LC + c0) * LQ;
    for (int i = t; i < CH * LQ; i += 256) {
        int c = i / 50, q = i - c * 50;
        Sraw_b[i] = Ssm[c * 51 + q];
    }
    // row softmax -> S_bar output (q-masked)
    const int qlen = g_qlen[b];
    float* outSB = out + (size_t)NB * LC * 4 * DD;
    for (int r = w; r < CH; r += 8) {
        int q2 = lane + 32;
        float v1 = Ssm[r * 51 + lane];
        float v2 = (q2 < LQ) ? Ssm[r * 51 + q2] : 0.f;
        float m = (lane < qlen) ? v1 : -1e30f;
        if (q2 < LQ && q2 < qlen) m = fmaxf(m, v2);
        #pragma unroll
        for (int o = 16; o; o >>= 1) m = fmaxf(m, __shfl_xor_sync(~0u, m, o));
        float e1 = (lane < qlen) ? __expf(v1 - m) : 0.f;
        float e2 = (q2 < LQ && q2 < qlen) ? __expf(v2 - m) : 0.f;
        float s = e1 + e2;
        #pragma unroll
        for (int o = 16; o; o >>= 1) s += __shfl_xor_sync(~0u, s, o);
        float r1 = 1.f / s;
        float* row = outSB + (size_t)(b * LC + c0 + r) * LQ;
        row[lane] = e1 * r1;
        if (q2 < LQ) row[q2] = e2 * r1;
    }
    // column partial stats (c-masked online softmax)
    const int clen = g_clen[b];
    for (int q = w; q < LQ; q += 8) {
        float m = -1e30f, s = 0.f;
        for (int cc = lane; cc < CH; cc += 32) {
            if (c0 + cc < clen) {
                float v = Ssm[cc * 51 + q];
                if (v > m) { s = s * __expf(m - v) + 1.f; m = v; }
                else       { s += __expf(v - m); }
            }
        }
        #pragma unroll
        for (int o = 16; o; o >>= 1) {
            float m2 = __shfl_xor_sync(~0u, m, o);
            float s2 = __shfl_xor_sync(~0u, s, o);
            if (m2 > m) { s = s * __expf(m - m2) + s2; m = m2; }
            else        { s += s2 * __expf(m2 - m); }
        }
        if (!lane) {
            float* p = d_cstatP + ((size_t)(b * 4 + blockIdx.x) * LQ + q) * 2;
            p[0] = m; p[1] = s;
        }
    }
}

// ---------------- K3: merge stats + S_T output + partial A = S_T @ x_cont ---
__global__ __launch_bounds__(512, 2)
void k3_stA(const float* __restrict__ g_xc, const int* __restrict__ g_clen,
            float* __restrict__ out)
{
    __shared__ __align__(16) float stT[CH * 51];
    __shared__ float mx[LQ], inv[LQ];
    const int b = blockIdx.y, chunk = blockIdx.x, c0 = chunk * CH;
    const int t = threadIdx.x, lane = t & 31, w = t >> 5;
    const int clen = g_clen[b];

    // merge the 4 partial column stats (was K2)
    if (t < LQ) {
        float m = -1e30f, s = 0.f;
        #pragma unroll
        for (int p = 0; p < 4; p++) {
            const float* pp = d_cstatP + ((size_t)(b * 4 + p) * LQ + t) * 2;
            float mp = pp[0], sp = pp[1];
            if (mp > m) { s = s * __expf(m - mp) + sp; m = mp; }
            else        { s += sp * __expf(mp - m); }
        }
        mx[t] = m; inv[t] = 1.f / s;
    }
    __syncthreads();

    const float* Sraw_b = d_Sraw + ((size_t)b * LC + c0) * LQ;
    for (int i = t; i < CH * LQ / 2; i += 512) {
        int cc = i / 25, q = 2 * (i - cc * 25);
        float2 v = *(const float2*)(Sraw_b + cc * 50 + q);
        bool ok = (c0 + cc) < clen;
        stT[cc * 51 + q]     = ok ? __expf(v.x - mx[q])     * inv[q]     : 0.f;
        stT[cc * 51 + q + 1] = ok ? __expf(v.y - mx[q + 1]) * inv[q + 1] : 0.f;
    }
    __syncthreads();
    // S_T output, q-major coalesced (float2)
    float* outST = out + (size_t)NB * LC * 4 * DD + (size_t)NB * LC * LQ;
    float* ST_b = outST + (size_t)b * LQ * LC + c0;
    for (int i = t; i < CH * LQ / 2; i += 512) {
        int q = i / 50, cc = 2 * (i - q * 50);
        float2 v = make_float2(stT[cc * 51 + q], stT[(cc + 1) * 51 + q]);
        *(float2*)(ST_b + (size_t)q * LC + cc) = v;
    }
    // partial A[q][d] += st[cc][q] * xc[c0+cc][d];  q = w + 16j
    const float* xcc = g_xc + ((size_t)b * LC + c0) * DD;
    const int nq = (w < 2) ? 4 : 3;
    ull accA[4][2];
    #pragma unroll
    for (int j = 0; j < 4; j++) { accA[j][0] = 0ull; accA[j][1] = 0ull; }
    #pragma unroll 1
    for (int cc = 0; cc < CH; cc++) {
        union { float4 f; ull u[2]; } X;
        X.f = *(const float4*)(xcc + (size_t)cc * DD + lane * 4);
        #pragma unroll
        for (int j = 0; j < 4; j++) {
            if (j < nq) {
                float sv = stT[cc * 51 + w + 16 * j];
                ull sb = pack2(sv, sv);
                fma2(accA[j][0], X.u[0], sb);
                fma2(accA[j][1], X.u[1], sb);
            }
        }
    }
    float* Ap = d_Apart + (size_t)(b * 4 + chunk) * LQ * DD;
    #pragma unroll
    for (int j = 0; j < 4; j++) {
        if (j < nq) {
            int q = w + 16 * j;
            union { float4 f; ull u[2]; } R;
            R.u[0] = accA[j][0]; R.u[1] = accA[j][1];
            *(float4*)(Ap + (size_t)q * DD + lane * 4) = R.f;
        }
    }
}

// ---------------- K4: c2q, q2c, fused concat --------------------------------
__global__ __launch_bounds__(512, 2)
void k4_final(const float* __restrict__ g_xc, const float* __restrict__ g_xq,
              float* __restrict__ out)
{
    extern __shared__ float sm4[];
    float* xqs = sm4;            // 50*132 = 6600
    float* As  = sm4 + 6600;     // 6600
    float* SB  = sm4 + 13200;    // 100*52 = 5200  (total 18400 fl = 73.6KB)
    const int b = blockIdx.y, c0 = blockIdx.x * CH;
    const int t = threadIdx.x, lane = t & 31, w = t >> 5;
    const float* xqb = g_xq + (size_t)b * LQ * DD;
    const float* xcb = g_xc + (size_t)b * LC * DD;
    float* outSB = out + (size_t)NB * LC * 4 * DD;

    for (int i = t; i < LQ * DD / 4; i += 512) {
        int q = i >> 5, dv = (i & 31) * 4;
        *(float4*)&xqs[q * 132 + dv] = *(const float4*)(xqb + q * DD + dv);
        float4 s = make_float4(0.f, 0.f, 0.f, 0.f);
        #pragma unroll
        for (int p = 0; p < 4; p++) {
            float4 v = *(const float4*)(d_Apart +
                        (size_t)(b * 4 + p) * LQ * DD + (size_t)q * DD + dv);
            s.x += v.x; s.y += v.y; s.z += v.z; s.w += v.w;
        }
        *(float4*)&As[q * 132 + dv] = s;
    }
    const float* SBg = outSB + ((size_t)b * LC + c0) * LQ;
    for (int i = t; i < CH * LQ / 2; i += 512) {
        int cc = i / 25, q = 2 * (i - cc * 25);
        float2 v = *(const float2*)(SBg + cc * 50 + q);
        *(float2*)&SB[cc * 52 + q] = v;
    }
    __syncthreads();

    const int nk = (w < 2) ? 4 : 3;
    #pragma unroll 1
    for (int half = 0; half < 2; half++) {
        ull a1[4][2], a2[4][2];
        #pragma unroll
        for (int k = 0; k < 4; k++) {
            a1[k][0] = a1[k][1] = 0ull;
            a2[k][0] = a2[k][1] = 0ull;
        }
        const int cbase = half * 50 + w;
        #pragma unroll 1
        for (int q = 0; q < LQ; q += 2) {
            union { float4 f; ull u[2]; } XQ0, AV0, XQ1, AV1;
            XQ0.f = *(const float4*)&xqs[q * 132 + lane * 4];
            AV0.f = *(const float4*)&As[q * 132 + lane * 4];
            XQ1.f = *(const float4*)&xqs[(q + 1) * 132 + lane * 4];
            AV1.f = *(const float4*)&As[(q + 1) * 132 + lane * 4];
            #pragma unroll
            for (int k = 0; k < 4; k++) {
                if (k < nk) {
                    float2 sv = *(const float2*)&SB[(cbase + 16 * k) * 52 + q];
                    ull s0 = pack2(sv.x, sv.x);
                    ull s1 = pack2(sv.y, sv.y);
                    fma2(a1[k][0], XQ0.u[0], s0);
                    fma2(a1[k][1], XQ0.u[1], s0);
                    fma2(a2[k][0], AV0.u[0], s0);
                    fma2(a2[k][1], AV0.u[1], s0);
                    fma2(a1[k][0], XQ1.u[0], s1);
                    fma2(a1[k][1], XQ1.u[1], s1);
                    fma2(a2[k][0], AV1.u[0], s1);
                    fma2(a2[k][1], AV1.u[1], s1);
                }
            }
        }
        #pragma unroll
        for (int k = 0; k < 4; k++) {
            if (k < nk) {
                int c = c0 + cbase + 16 * k;
                float4 xcv = *(const float4*)(xcb + (size_t)c * DD + lane * 4);
                union { float4 f; ull u[2]; } C2Q, Q2C;
                C2Q.u[0] = a1[k][0]; C2Q.u[1] = a1[k][1];
                Q2C.u[0] = a2[k][0]; Q2C.u[1] = a2[k][1];
                float* base = out + ((size_t)b * LC + c) * (4 * DD) + lane * 4;
                *(float4*)(base)       = xcv;
                *(float4*)(base + 128) = C2Q.f;
                *(float4*)(base + 256) = make_float4(xcv.x * C2Q.f.x, xcv.y * C2Q.f.y,
                                                     xcv.z * C2Q.f.z, xcv.w * C2Q.f.w);
                *(float4*)(base + 384) = make_float4(xcv.x * Q2C.f.x, xcv.y * Q2C.f.y,
                                                     xcv.z * Q2C.f.z, xcv.w * Q2C.f.w);
            }
        }
    }
}

extern "C" void kernel_launch(void* const* d_in, const int* in_sizes, int n_in,
                              void* d_out, int out_size)
{
    const float* xc  = (const float*)d_in[0];
    const float* xq  = (const float*)d_in[1];
    const float* W0  = (const float*)d_in[2];
    const float* W1  = (const float*)d_in[3];
    const float* W2  = (const float*)d_in[4];
    const int* clen  = (const int*)d_in[5];
    const int* qlen  = (const int*)d_in[6];
    float* out = (float*)d_out;

    cudaFuncSetAttribute(k4_final, cudaFuncAttributeMaxDynamicSharedMemorySize,
                         18400 * (int)sizeof(float));

    dim3 g(4, NB);
    k1_score<<<g, 256>>>(xc, xq, W0, W1, W2, clen, qlen, out);
    k3_stA<<<g, 512>>>(xc, clen, out);
    k4_final<<<g, 512, 18400 * sizeof(float)>>>(xc, xq, out);
}

// round 6
// speedup vs baseline: 1.1663x; 1.1663x over previous
#include <cuda_runtime.h>

typedef unsigned long long ull;

__device__ __forceinline__ ull pack2(float lo, float hi) {
    ull r; asm("mov.b64 %0, {%1, %2};" : "=l"(r) : "f"(lo), "f"(hi)); return r;
}
__device__ __forceinline__ void unpack2(ull v, float& lo, float& hi) {
    asm("mov.b64 {%0, %1}, %2;" : "=f"(lo), "=f"(hi) : "l"(v));
}
__device__ __forceinline__ void fma2(ull& d, ull a, ull b) {
    asm("fma.rn.f32x2 %0, %1, %2, %0;" : "+l"(d) : "l"(a), "l"(b));
}

#define NB 256
#define LC 400
#define LQ 50
#define DD 128

// smem layout (floats): S 20000 | A/staging 6600 | sc 400 | sq 52 | mxc 52 | invc 52
#define SM_TOT 27156

__global__ __launch_bounds__(512, 2)
void cqa2_kernel(const float* __restrict__ g_xc, const float* __restrict__ g_xq,
                 const float* __restrict__ g_W0, const float* __restrict__ g_W1,
                 const float* __restrict__ g_W2, const int* __restrict__ g_clen,
                 const int* __restrict__ g_qlen, float* __restrict__ out)
{
    extern __shared__ float sm[];
    float* S    = sm;            // 400*50 packed
    float* A    = sm + 20000;    // 6600: phase1 staging / phase3 stb / phase6 A(50x132)
    float* sc   = sm + 26600;
    float* sq   = sm + 27000;
    float* mxc  = sm + 27052;
    float* invc = sm + 27104;

    float* xcT = A;              // 8*402 = 3216 (phase 1)
    float* xqT = A + 3216;       // 8*51  = 408
    float* stb = A;              // 50*65 = 3250 (phase 3)

    const int b = blockIdx.x;
    const int t = threadIdx.x, lane = t & 31, w = t >> 5;
    const float* xcb = g_xc + (size_t)b * LC * DD;
    const float* xqb = g_xq + (size_t)b * LQ * DD;
    const int clen = g_clen[b];
    const int qlen = g_qlen[b];

    float* outSB = out + (size_t)NB * LC * 4 * DD;
    float* outST = outSB + (size_t)NB * LC * LQ;

    // ---------------- Phase 0: sc[c] = xc.W0, sq[q] = xq.W1 ------------------
    {
        float4 w0 = __ldg((const float4*)g_W0 + lane);
        #pragma unroll 1
        for (int r = 0; r < 25; r++) {
            int c = w + 16 * r;
            float4 v = __ldg((const float4*)(xcb + (size_t)c * DD) + lane);
            float p = v.x * w0.x + v.y * w0.y + v.z * w0.z + v.w * w0.w;
            #pragma unroll
            for (int o = 16; o; o >>= 1) p += __shfl_xor_sync(~0u, p, o);
            if (!lane) sc[c] = p;
        }
        float4 w1 = __ldg((const float4*)g_W1 + lane);
        #pragma unroll
        for (int r = 0; r < 4; r++) {
            int q = w + 16 * r;
            if (q < LQ) {
                float4 v = __ldg((const float4*)(xqb + (size_t)q * DD) + lane);
                float p = v.x * w1.x + v.y * w1.y + v.z * w1.z + v.w * w1.w;
                #pragma unroll
                for (int o = 16; o; o >>= 1) p += __shfl_xor_sync(~0u, p, o);
                if (!lane) sq[q] = p;
            }
        }
    }

    // ---------------- Phase 1: S = (xc*W2) @ xq^T  (+sc+sq at writeback) -----
    ull acc[4][5];
    #pragma unroll
    for (int i = 0; i < 4; i++)
        #pragma unroll
        for (int j = 0; j < 5; j++) acc[i][j] = 0ull;
    const int ct = t / 10, qt = t - ct * 10;
    const bool act = t < 500;
    const int cb = ct * 8, qb = qt * 5;

    #pragma unroll 1
    for (int s8 = 0; s8 < 16; s8++) {
        const int d0 = s8 * 8;
        __syncthreads();
        if (t < 400) {
            int q = t >> 3, dd = t & 7;
            xqT[dd * 51 + q] = xqb[q * DD + d0 + dd];
        }
        for (int i = t; i < LC * 8; i += 512) {
            int c = i >> 3, dd = i & 7;
            xcT[dd * 402 + c] = xcb[(size_t)c * DD + d0 + dd] * __ldg(g_W2 + d0 + dd);
        }
        __syncthreads();
        if (act) {
            #pragma unroll
            for (int dd = 0; dd < 8; dd++) {
                ull a0 = *(const ull*)&xcT[dd * 402 + cb];
                ull a1 = *(const ull*)&xcT[dd * 402 + cb + 2];
                ull a2 = *(const ull*)&xcT[dd * 402 + cb + 4];
                ull a3 = *(const ull*)&xcT[dd * 402 + cb + 6];
                #pragma unroll
                for (int j = 0; j < 5; j++) {
                    float xv = xqT[dd * 51 + qb + j];
                    ull bb = pack2(xv, xv);
                    fma2(acc[0][j], a0, bb);
                    fma2(acc[1][j], a1, bb);
                    fma2(acc[2][j], a2, bb);
                    fma2(acc[3][j], a3, bb);
                }
            }
        }
    }
    __syncthreads();
    if (act) {
        #pragma unroll
        for (int i = 0; i < 4; i++) {
            int c = cb + 2 * i;
            float s0 = sc[c], s1 = sc[c + 1];
            #pragma unroll
            for (int j = 0; j < 5; j++) {
                float lo, hi; unpack2(acc[i][j], lo, hi);
                int q = qb + j;
                S[c * 50 + q]       = lo + s0 + sq[q];
                S[(c + 1) * 50 + q] = hi + s1 + sq[q];
            }
        }
    }
    __syncthreads();

    // ---------------- Phase 2: column (over c) softmax stats -----------------
    #pragma unroll 1
    for (int r = 0; r < 4; r++) {
        int q = w + 16 * r;
        if (q < LQ) {
            float m = -1e30f, s = 0.f;
            for (int c = lane; c < clen; c += 32) {
                float v = S[c * 50 + q];
                if (v > m) { s = s * __expf(m - v) + 1.f; m = v; }
                else       { s += __expf(v - m); }
            }
            #pragma unroll
            for (int o = 16; o; o >>= 1) {
                float m2 = __shfl_xor_sync(~0u, m, o);
                float s2 = __shfl_xor_sync(~0u, s, o);
                if (m2 > m) { s = s * __expf(m - m2) + s2; m = m2; }
                else        { s += s2 * __expf(m2 - m); }
            }
            if (!lane) { mxc[q] = m; invc[q] = 1.f / s; }
        }
    }
    __syncthreads();

    // ---------------- Phase 3: S_T out + A = S_T @ x_cont (regs) -------------
    {
        const int nq = (w < 2) ? 4 : 3;   // q = w + 16j
        ull accA[4][2];
        #pragma unroll
        for (int j = 0; j < 4; j++) { accA[j][0] = 0ull; accA[j][1] = 0ull; }
        float* ST_b = outST + (size_t)b * LQ * LC;

        #pragma unroll 1
        for (int c0 = 0; c0 < LC; c0 += 64) {
            const int CHN = (LC - c0 >= 64) ? 64 : 16;
            __syncthreads();
            if (CHN == 64) {
                for (int i = t; i < LQ * 64; i += 512) {
                    int q = i >> 6, cc = i & 63, c = c0 + cc;
                    float v = (c < clen) ? __expf(S[c * 50 + q] - mxc[q]) * invc[q] : 0.f;
                    stb[q * 65 + cc] = v;
                    ST_b[(size_t)q * LC + c] = v;
                }
            } else {
                for (int i = t; i < LQ * 16; i += 512) {
                    int q = i >> 4, cc = i & 15, c = c0 + cc;
                    float v = (c < clen) ? __expf(S[c * 50 + q] - mxc[q]) * invc[q] : 0.f;
                    stb[q * 65 + cc] = v;
                    ST_b[(size_t)q * LC + c] = v;
                }
            }
            __syncthreads();
            #pragma unroll 1
            for (int cc = 0; cc < CHN; cc++) {
                union { float4 f; ull u[2]; } X;
                X.f = __ldg((const float4*)(xcb + (size_t)(c0 + cc) * DD) + lane);
                #pragma unroll
                for (int j = 0; j < 4; j++) {
                    if (j < nq) {
                        float sv = stb[(w + 16 * j) * 65 + cc];
                        ull sb = pack2(sv, sv);
                        fma2(accA[j][0], X.u[0], sb);
                        fma2(accA[j][1], X.u[1], sb);
                    }
                }
            }
        }
        __syncthreads();   // stb dead; A region reusable
        #pragma unroll
        for (int j = 0; j < 4; j++) {
            if (j < nq) {
                union { float4 f; ull u[2]; } R;
                R.u[0] = accA[j][0]; R.u[1] = accA[j][1];
                *(float4*)&A[(w + 16 * j) * 132 + lane * 4] = R.f;
            }
        }
    }
    __syncthreads();

    // ---------------- Phase 4: row softmax -> S_bar in place -----------------
    #pragma unroll 1
    for (int r = 0; r < 25; r++) {
        int c = w + 16 * r;
        int q2 = lane + 32;
        float v1 = S[c * 50 + lane];
        float v2 = (q2 < LQ) ? S[c * 50 + q2] : 0.f;
        float m = (lane < qlen) ? v1 : -1e30f;
        if (q2 < LQ && q2 < qlen) m = fmaxf(m, v2);
        #pragma unroll
        for (int o = 16; o; o >>= 1) m = fmaxf(m, __shfl_xor_sync(~0u, m, o));
        float e1 = (lane < qlen) ? __expf(v1 - m) : 0.f;
        float e2 = (q2 < LQ && q2 < qlen) ? __expf(v2 - m) : 0.f;
        float s = e1 + e2;
        #pragma unroll
        for (int o = 16; o; o >>= 1) s += __shfl_xor_sync(~0u, s, o);
        float r1 = 1.f / s;
        e1 *= r1; e2 *= r1;
        S[c * 50 + lane] = e1;
        float* row = outSB + (size_t)(b * LC + c) * LQ;
        row[lane] = e1;
        if (q2 < LQ) { S[c * 50 + q2] = e2; row[q2] = e2; }
    }
    __syncthreads();

    // ---------------- Phase 5: c2q = Sbar@xq, q2c = Sbar@A, concat -----------
    #pragma unroll 1
    for (int pass = 0; pass < 7; pass++) {
        const int kmax = (pass < 6) ? 4 : 1;
        ull a1[4][2], a2[4][2];
        #pragma unroll
        for (int k = 0; k < 4; k++) {
            a1[k][0] = a1[k][1] = 0ull;
            a2[k][0] = a2[k][1] = 0ull;
        }
        const int cbase = pass * 64 + w;
        #pragma unroll 1
        for (int q = 0; q < LQ; q++) {
            union { float4 f; ull u[2]; } XQ, AV;
            XQ.f = __ldg((const float4*)(xqb + (size_t)q * DD) + lane);
            AV.f = *(const float4*)&A[q * 132 + lane * 4];
            #pragma unroll
            for (int k = 0; k < 4; k++) {
                if (k < kmax) {
                    float sb = S[(cbase + 16 * k) * 50 + q];  // broadcast
                    ull sp = pack2(sb, sb);
                    fma2(a1[k][0], XQ.u[0], sp);
                    fma2(a1[k][1], XQ.u[1], sp);
                    fma2(a2[k][0], AV.u[0], sp);
                    fma2(a2[k][1], AV.u[1], sp);
                }
            }
        }
        #pragma unroll
        for (int k = 0; k < 4; k++) {
            if (k < kmax) {
                int c = cbase + 16 * k;
                float4 xcv = __ldg((const float4*)(xcb + (size_t)c * DD) + lane);
                union { float4 f; ull u[2]; } C2Q, Q2C;
                C2Q.u[0] = a1[k][0]; C2Q.u[1] = a1[k][1];
                Q2C.u[0] = a2[k][0]; Q2C.u[1] = a2[k][1];
                float* base = out + ((size_t)b * LC + c) * (4 * DD) + lane * 4;
                *(float4*)(base)       = xcv;
                *(float4*)(base + 128) = C2Q.f;
                *(float4*)(base + 256) = make_float4(xcv.x * C2Q.f.x, xcv.y * C2Q.f.y,
                                                     xcv.z * C2Q.f.z, xcv.w * C2Q.f.w);
                *(float4*)(base + 384) = make_float4(xcv.x * Q2C.f.x, xcv.y * Q2C.f.y,
                                                     xcv.z * Q2C.f.z, xcv.w * Q2C.f.w);
            }
        }
    }
}

extern "C" void kernel_launch(void* const* d_in, const int* in_sizes, int n_in,
                              void* d_out, int out_size)
{
    const float* xc  = (const float*)d_in[0];
    const float* xq  = (const float*)d_in[1];
    const float* W0  = (const float*)d_in[2];
    const float* W1  = (const float*)d_in[3];
    const float* W2  = (const float*)d_in[4];
    const int* clen  = (const int*)d_in[5];
    const int* qlen  = (const int*)d_in[6];
    float* out = (float*)d_out;

    const size_t smem = (size_t)SM_TOT * sizeof(float);  // 108624 B
    cudaFuncSetAttribute(cqa2_kernel, cudaFuncAttributeMaxDynamicSharedMemorySize,
                         (int)smem);
    cqa2_kernel<<<NB, 512, smem>>>(xc, xq, W0, W1, W2, clen, qlen, out);
}

// round 7
// speedup vs baseline: 1.4092x; 1.2083x over previous
#include <cuda_runtime.h>
#include <cstdint>

typedef unsigned long long ull;

__device__ __forceinline__ ull pack2(float lo, float hi) {
    ull r; asm("mov.b64 %0, {%1, %2};" : "=l"(r) : "f"(lo), "f"(hi)); return r;
}
__device__ __forceinline__ void unpack2(ull v, float& lo, float& hi) {
    asm("mov.b64 {%0, %1}, %2;" : "=f"(lo), "=f"(hi) : "l"(v));
}
__device__ __forceinline__ void fma2(ull& d, ull a, ull b) {
    asm("fma.rn.f32x2 %0, %1, %2, %0;" : "+l"(d) : "l"(a), "l"(b));
}
__device__ __forceinline__ uint32_t s2u(const void* p) {
    return (uint32_t)__cvta_generic_to_shared(p);
}
__device__ __forceinline__ void cpa4(uint32_t dst, const float* src) {
    asm volatile("cp.async.ca.shared.global [%0], [%1], 4;" :: "r"(dst), "l"(src));
}
#define CP_COMMIT() asm volatile("cp.async.commit_group;" ::: "memory")
#define CP_WAIT0()  asm volatile("cp.async.wait_group 0;" ::: "memory")

#define NB 256
#define LC 400
#define LQ 50
#define DD 128
#define SM_TOT 27156   // floats: S 20000 | A/stb 6600 | sc 400 | sq 52 | mxc 52 | invc 52

__global__ __launch_bounds__(512, 2)
void cqa3_kernel(const float* __restrict__ g_xc, const float* __restrict__ g_xq,
                 const float* __restrict__ g_W0, const float* __restrict__ g_W1,
                 const float* __restrict__ g_W2, const int* __restrict__ g_clen,
                 const int* __restrict__ g_qlen, float* __restrict__ out)
{
    extern __shared__ float sm[];
    float* S    = sm;            // 400*50 packed
    float* A    = sm + 20000;    // 6600: phase3 stb (50x65) / phase5 A (50x132)
    float* sc   = sm + 26600;
    float* sq   = sm + 27000;
    float* mxc  = sm + 27052;
    float* invc = sm + 27104;
    // phase-1 staging lives inside S (dead until phase-1 writeback)
    float* stA0 = S;             // 8*402 = 3216
    float* stA1 = S + 3216;      // 3216
    float* stQ0 = S + 6432;      // 8*51  = 408
    float* stQ1 = S + 6840;      // 408

    const int b = blockIdx.x;
    const int t = threadIdx.x, lane = t & 31, w = t >> 5;
    const float* xcb = g_xc + (size_t)b * LC * DD;
    const float* xqb = g_xq + (size_t)b * LQ * DD;
    const int clen = g_clen[b];
    const int qlen = g_qlen[b];

    float* outSB = out + (size_t)NB * LC * 4 * DD;
    float* outST = outSB + (size_t)NB * LC * LQ;

    // ---------------- Phase 0: sc[c] = xc.W0, sq[q] = xq.W1 ------------------
    {
        float4 w0 = __ldg((const float4*)g_W0 + lane);
        #pragma unroll 1
        for (int r = 0; r < 25; r++) {
            int c = w + 16 * r;
            float4 v = __ldg((const float4*)(xcb + (size_t)c * DD) + lane);
            float p = v.x * w0.x + v.y * w0.y + v.z * w0.z + v.w * w0.w;
            #pragma unroll
            for (int o = 16; o; o >>= 1) p += __shfl_xor_sync(~0u, p, o);
            if (!lane) sc[c] = p;
        }
        float4 w1 = __ldg((const float4*)g_W1 + lane);
        #pragma unroll
        for (int r = 0; r < 4; r++) {
            int q = w + 16 * r;
            if (q < LQ) {
                float4 v = __ldg((const float4*)(xqb + (size_t)q * DD) + lane);
                float p = v.x * w1.x + v.y * w1.y + v.z * w1.z + v.w * w1.w;
                #pragma unroll
                for (int o = 16; o; o >>= 1) p += __shfl_xor_sync(~0u, p, o);
                if (!lane) sq[q] = p;
            }
        }
    }

    // ---------------- Phase 1: S = xc @ (W2*xq)^T, cp.async double-buffered --
    ull acc[4][5];
    #pragma unroll
    for (int i = 0; i < 4; i++)
        #pragma unroll
        for (int j = 0; j < 5; j++) acc[i][j] = 0ull;
    const int ct = t / 10, qt = t - ct * 10;
    const bool act = t < 500;
    const int cb = ct * 8, qb = qt * 5;

    // issue staging for slice s: xc slice (pure copy, cp.async, transposed)
    // and xq slice (*W2, plain STS)
    auto issue = [&](int s) {
        const int d0 = s * 8;
        float* bA = (s & 1) ? stA1 : stA0;
        float* bQ = (s & 1) ? stQ1 : stQ0;
        #pragma unroll 1
        for (int i = t; i < LC * 8; i += 512) {
            int c = i >> 3, dd = i & 7;
            cpa4(s2u(bA + dd * 402 + c), xcb + (size_t)c * DD + d0 + dd);
        }
        CP_COMMIT();
        if (t < 400) {
            int q = t >> 3, dd = t & 7;
            bQ[dd * 51 + q] = xqb[q * DD + d0 + dd] * __ldg(g_W2 + d0 + dd);
        }
    };

    __syncthreads();   // phase-0 writers of sc/sq... (sc/sq not in S region; safe)
    issue(0);
    #pragma unroll 1
    for (int s = 0; s < 16; s++) {
        CP_WAIT0();
        __syncthreads();            // slice s staged & visible; prev compute done
        if (s < 15) issue(s + 1);   // overlaps with compute below
        const float* bA = (s & 1) ? stA1 : stA0;
        const float* bQ = (s & 1) ? stQ1 : stQ0;
        if (act) {
            #pragma unroll
            for (int dd = 0; dd < 8; dd++) {
                ull a0 = *(const ull*)&bA[dd * 402 + cb];
                ull a1 = *(const ull*)&bA[dd * 402 + cb + 2];
                ull a2 = *(const ull*)&bA[dd * 402 + cb + 4];
                ull a3 = *(const ull*)&bA[dd * 402 + cb + 6];
                #pragma unroll
                for (int j = 0; j < 5; j++) {
                    float xv = bQ[dd * 51 + qb + j];
                    ull bb = pack2(xv, xv);
                    fma2(acc[0][j], a0, bb);
                    fma2(acc[1][j], a1, bb);
                    fma2(acc[2][j], a2, bb);
                    fma2(acc[3][j], a3, bb);
                }
            }
        }
    }
    __syncthreads();
    if (act) {
        #pragma unroll
        for (int i = 0; i < 4; i++) {
            int c = cb + 2 * i;
            float s0 = sc[c], s1 = sc[c + 1];
            #pragma unroll
            for (int j = 0; j < 5; j++) {
                float lo, hi; unpack2(acc[i][j], lo, hi);
                int q = qb + j;
                S[c * 50 + q]       = lo + s0 + sq[q];
                S[(c + 1) * 50 + q] = hi + s1 + sq[q];
            }
        }
    }
    __syncthreads();

    // ---------------- Phase 2: column (over c) softmax stats -----------------
    #pragma unroll 1
    for (int r = 0; r < 4; r++) {
        int q = w + 16 * r;
        if (q < LQ) {
            float m = -1e30f, s = 0.f;
            for (int c = lane; c < clen; c += 32) {
                float v = S[c * 50 + q];
                if (v > m) { s = s * __expf(m - v) + 1.f; m = v; }
                else       { s += __expf(v - m); }
            }
            #pragma unroll
            for (int o = 16; o; o >>= 1) {
                float m2 = __shfl_xor_sync(~0u, m, o);
                float s2 = __shfl_xor_sync(~0u, s, o);
                if (m2 > m) { s = s * __expf(m - m2) + s2; m = m2; }
                else        { s += s2 * __expf(m2 - m); }
            }
            if (!lane) { mxc[q] = m; invc[q] = 1.f / s; }
        }
    }
    __syncthreads();

    // ---------------- Phase 3: S_T out + A = S_T @ x_cont (regs) -------------
    {
        float* stb = A;   // 50*65
        const int nq = (w < 2) ? 4 : 3;   // q = w + 16j
        ull accA[4][2];
        #pragma unroll
        for (int j = 0; j < 4; j++) { accA[j][0] = 0ull; accA[j][1] = 0ull; }
        float* ST_b = outST + (size_t)b * LQ * LC;

        #pragma unroll 1
        for (int c0 = 0; c0 < LC; c0 += 64) {
            const int CHN = (LC - c0 >= 64) ? 64 : 16;
            __syncthreads();
            if (CHN == 64) {
                for (int i = t; i < LQ * 64; i += 512) {
                    int q = i >> 6, cc = i & 63, c = c0 + cc;
                    float v = (c < clen) ? __expf(S[c * 50 + q] - mxc[q]) * invc[q] : 0.f;
                    stb[q * 65 + cc] = v;
                    ST_b[(size_t)q * LC + c] = v;
                }
            } else {
                for (int i = t; i < LQ * 16; i += 512) {
                    int q = i >> 4, cc = i & 15, c = c0 + cc;
                    float v = (c < clen) ? __expf(S[c * 50 + q] - mxc[q]) * invc[q] : 0.f;
                    stb[q * 65 + cc] = v;
                    ST_b[(size_t)q * LC + c] = v;
                }
            }
            __syncthreads();
            #pragma unroll 1
            for (int cc = 0; cc < CHN; cc += 2) {
                union { float4 f; ull u[2]; } X0, X1;
                X0.f = __ldg((const float4*)(xcb + (size_t)(c0 + cc) * DD) + lane);
                X1.f = __ldg((const float4*)(xcb + (size_t)(c0 + cc + 1) * DD) + lane);
                #pragma unroll
                for (int j = 0; j < 4; j++) {
                    if (j < nq) {
                        float s0 = stb[(w + 16 * j) * 65 + cc];
                        float s1 = stb[(w + 16 * j) * 65 + cc + 1];
                        ull p0 = pack2(s0, s0), p1 = pack2(s1, s1);
                        fma2(accA[j][0], X0.u[0], p0);
                        fma2(accA[j][1], X0.u[1], p0);
                        fma2(accA[j][0], X1.u[0], p1);
                        fma2(accA[j][1], X1.u[1], p1);
                    }
                }
            }
        }
        __syncthreads();   // stb dead; A region reusable
        #pragma unroll
        for (int j = 0; j < 4; j++) {
            if (j < nq) {
                union { float4 f; ull u[2]; } R;
                R.u[0] = accA[j][0]; R.u[1] = accA[j][1];
                *(float4*)&A[(w + 16 * j) * 132 + lane * 4] = R.f;
            }
        }
    }
    __syncthreads();

    // ---------------- Phase 4: row softmax -> S_bar in place -----------------
    #pragma unroll 1
    for (int r = 0; r < 25; r++) {
        int c = w + 16 * r;
        int q2 = lane + 32;
        float v1 = S[c * 50 + lane];
        float v2 = (q2 < LQ) ? S[c * 50 + q2] : 0.f;
        float m = (lane < qlen) ? v1 : -1e30f;
        if (q2 < LQ && q2 < qlen) m = fmaxf(m, v2);
        #pragma unroll
        for (int o = 16; o; o >>= 1) m = fmaxf(m, __shfl_xor_sync(~0u, m, o));
        float e1 = (lane < qlen) ? __expf(v1 - m) : 0.f;
        float e2 = (q2 < LQ && q2 < qlen) ? __expf(v2 - m) : 0.f;
        float s = e1 + e2;
        #pragma unroll
        for (int o = 16; o; o >>= 1) s += __shfl_xor_sync(~0u, s, o);
        float r1 = 1.f / s;
        e1 *= r1; e2 *= r1;
        S[c * 50 + lane] = e1;
        float* row = outSB + (size_t)(b * LC + c) * LQ;
        row[lane] = e1;
        if (q2 < LQ) { S[c * 50 + q2] = e2; row[q2] = e2; }
    }
    __syncthreads();

    // ---------------- Phase 5: c2q = Sbar@xq, q2c = Sbar@A, concat -----------
    #pragma unroll 1
    for (int pass = 0; pass < 7; pass++) {
        const int kmax = (pass < 6) ? 4 : 1;
        ull a1[4][2], a2[4][2];
        #pragma unroll
        for (int k = 0; k < 4; k++) {
            a1[k][0] = a1[k][1] = 0ull;
            a2[k][0] = a2[k][1] = 0ull;
        }
        const int cbase = pass * 64 + w;
        #pragma unroll 1
        for (int q = 0; q < LQ; q += 2) {
            union { float4 f; ull u[2]; } XQ0, XQ1, AV0, AV1;
            XQ0.f = __ldg((const float4*)(xqb + (size_t)q * DD) + lane);
            XQ1.f = __ldg((const float4*)(xqb + (size_t)(q + 1) * DD) + lane);
            AV0.f = *(const float4*)&A[q * 132 + lane * 4];
            AV1.f = *(const float4*)&A[(q + 1) * 132 + lane * 4];
            #pragma unroll
            for (int k = 0; k < 4; k++) {
                if (k < kmax) {
                    float2 sv = *(const float2*)&S[(cbase + 16 * k) * 50 + q];
                    ull s0 = pack2(sv.x, sv.x);
                    ull s1 = pack2(sv.y, sv.y);
                    fma2(a1[k][0], XQ0.u[0], s0);
                    fma2(a1[k][1], XQ0.u[1], s0);
                    fma2(a2[k][0], AV0.u[0], s0);
                    fma2(a2[k][1], AV0.u[1], s0);
                    fma2(a1[k][0], XQ1.u[0], s1);
                    fma2(a1[k][1], XQ1.u[1], s1);
                    fma2(a2[k][0], AV1.u[0], s1);
                    fma2(a2[k][1], AV1.u[1], s1);
                }
            }
        }
        #pragma unroll
        for (int k = 0; k < 4; k++) {
            if (k < kmax) {
                int c = cbase + 16 * k;
                float4 xcv = __ldg((const float4*)(xcb + (size_t)c * DD) + lane);
                union { float4 f; ull u[2]; } C2Q, Q2C;
                C2Q.u[0] = a1[k][0]; C2Q.u[1] = a1[k][1];
                Q2C.u[0] = a2[k][0]; Q2C.u[1] = a2[k][1];
                float* base = out + ((size_t)b * LC + c) * (4 * DD) + lane * 4;
                *(float4*)(base)       = xcv;
                *(float4*)(base + 128) = C2Q.f;
                *(float4*)(base + 256) = make_float4(xcv.x * C2Q.f.x, xcv.y * C2Q.f.y,
                                                     xcv.z * C2Q.f.z, xcv.w * C2Q.f.w);
                *(float4*)(base + 384) = make_float4(xcv.x * Q2C.f.x, xcv.y * Q2C.f.y,
                                                     xcv.z * Q2C.f.z, xcv.w * Q2C.f.w);
            }
        }
    }
}

extern "C" void kernel_launch(void* const* d_in, const int* in_sizes, int n_in,
                              void* d_out, int out_size)
{
    const float* xc  = (const float*)d_in[0];
    const float* xq  = (const float*)d_in[1];
    const float* W0  = (const float*)d_in[2];
    const float* W1  = (const float*)d_in[3];
    const float* W2  = (const float*)d_in[4];
    const int* clen  = (const int*)d_in[5];
    const int* qlen  = (const int*)d_in[6];
    float* out = (float*)d_out;

    const size_t smem = (size_t)SM_TOT * sizeof(float);  // 108624 B
    cudaFuncSetAttribute(cqa3_kernel, cudaFuncAttributeMaxDynamicSharedMemorySize,
                         (int)smem);
    cqa3_kernel<<<NB, 512, smem>>>(xc, xq, W0, W1, W2, clen, qlen, out);
}

// round 10
// speedup vs baseline: 1.4257x; 1.0117x over previous
#include <cuda_runtime.h>
#include <cstdint>

typedef unsigned long long ull;

__device__ __forceinline__ ull pack2(float lo, float hi) {
    ull r; asm("mov.b64 %0, {%1, %2};" : "=l"(r) : "f"(lo), "f"(hi)); return r;
}
__device__ __forceinline__ void unpack2(ull v, float& lo, float& hi) {
    asm("mov.b64 {%0, %1}, %2;" : "=f"(lo), "=f"(hi) : "l"(v));
}
__device__ __forceinline__ void fma2(ull& d, ull a, ull b) {
    asm("fma.rn.f32x2 %0, %1, %2, %0;" : "+l"(d) : "l"(a), "l"(b));
}
__device__ __forceinline__ uint32_t s2u(const void* p) {
    return (uint32_t)__cvta_generic_to_shared(p);
}
__device__ __forceinline__ void cpa4(uint32_t dst, const float* src) {
    asm volatile("cp.async.ca.shared.global [%0], [%1], 4;" :: "r"(dst), "l"(src));
}
#define CP_COMMIT() asm volatile("cp.async.commit_group;" ::: "memory")
#define CP_WAIT0()  asm volatile("cp.async.wait_group 0;" ::: "memory")

#define NB 256
#define LC 400
#define LQ 50
#define DD 128
#define SM_TOT 27156   // floats: S 20000 | A/stb 6600 | sc 400 | sq 52 | mxc 52 | invc 52

__global__ __launch_bounds__(512, 2)
void cqa4_kernel(const float* __restrict__ g_xc, const float* __restrict__ g_xq,
                 const float* __restrict__ g_W0, const float* __restrict__ g_W1,
                 const float* __restrict__ g_W2, const int* __restrict__ g_clen,
                 const int* __restrict__ g_qlen, float* __restrict__ out)
{
    extern __shared__ float sm[];
    float* S    = sm;            // 400*50 packed
    float* A    = sm + 20000;    // 6600: phase3 stb (50x129) / phase5 A (50x132)
    float* sc   = sm + 26600;
    float* sq   = sm + 27000;
    float* mxc  = sm + 27052;
    float* invc = sm + 27104;
    // phase-1 staging lives inside S (dead until phase-1 writeback)
    float* stA0 = S;             // 8*404 = 3232 (16B-aligned rows)
    float* stA1 = S + 3232;
    float* stQ0 = S + 6464;      // 8*51 = 408
    float* stQ1 = S + 6872;

    const int b = blockIdx.x;
    const int t = threadIdx.x, lane = t & 31, w = t >> 5;
    const float* xcb = g_xc + (size_t)b * LC * DD;
    const float* xqb = g_xq + (size_t)b * LQ * DD;
    const int clen = g_clen[b];
    const int qlen = g_qlen[b];

    float* outSB = out + (size_t)NB * LC * 4 * DD;
    float* outST = outSB + (size_t)NB * LC * LQ;

    // ---------------- Phase 0: sc[c] = xc.W0, sq[q] = xq.W1 ------------------
    {
        float4 w0 = __ldg((const float4*)g_W0 + lane);
        #pragma unroll 1
        for (int r = 0; r < 25; r++) {
            int c = w + 16 * r;
            float4 v = __ldg((const float4*)(xcb + (size_t)c * DD) + lane);
            float p = v.x * w0.x + v.y * w0.y + v.z * w0.z + v.w * w0.w;
            #pragma unroll
            for (int o = 16; o; o >>= 1) p += __shfl_xor_sync(~0u, p, o);
            if (!lane) sc[c] = p;
        }
        float4 w1 = __ldg((const float4*)g_W1 + lane);
        #pragma unroll
        for (int r = 0; r < 4; r++) {
            int q = w + 16 * r;
            if (q < LQ) {
                float4 v = __ldg((const float4*)(xqb + (size_t)q * DD) + lane);
                float p = v.x * w1.x + v.y * w1.y + v.z * w1.z + v.w * w1.w;
                #pragma unroll
                for (int o = 16; o; o >>= 1) p += __shfl_xor_sync(~0u, p, o);
                if (!lane) sq[q] = p;
            }
        }
    }

    // ---------------- Phase 1: S = xc @ (W2*xq)^T, cp.async double-buffered --
    ull acc[4][5];
    #pragma unroll
    for (int i = 0; i < 4; i++)
        #pragma unroll
        for (int j = 0; j < 5; j++) acc[i][j] = 0ull;
    const int ct = t / 10, qt = t - ct * 10;
    const bool act = t < 500;
    const int cb = ct * 8, qb = qt * 5;

    auto issue = [&](int s) {
        const int d0 = s * 8;
        float* bA = (s & 1) ? stA1 : stA0;
        float* bQ = (s & 1) ? stQ1 : stQ0;
        #pragma unroll 1
        for (int i = t; i < LC * 8; i += 512) {
            int c = i >> 3, dd = i & 7;
            cpa4(s2u(bA + dd * 404 + c), xcb + (size_t)c * DD + d0 + dd);
        }
        CP_COMMIT();
        if (t < 400) {
            int q = t >> 3, dd = t & 7;
            bQ[dd * 51 + q] = xqb[q * DD + d0 + dd] * __ldg(g_W2 + d0 + dd);
        }
    };

    __syncthreads();
    issue(0);
    #pragma unroll 1
    for (int s = 0; s < 16; s++) {
        CP_WAIT0();
        __syncthreads();            // slice s staged & visible; prev compute done
        if (s < 15) issue(s + 1);   // overlaps with compute below
        const float* bA = (s & 1) ? stA1 : stA0;
        const float* bQ = (s & 1) ? stQ1 : stQ0;
        if (act) {
            #pragma unroll
            for (int dd = 0; dd < 8; dd++) {
                union { float4 f; ull u[2]; } X0, X1;
                X0.f = *(const float4*)&bA[dd * 404 + cb];
                X1.f = *(const float4*)&bA[dd * 404 + cb + 4];
                #pragma unroll
                for (int j = 0; j < 5; j++) {
                    float xv = bQ[dd * 51 + qb + j];
                    ull bb = pack2(xv, xv);
                    fma2(acc[0][j], X0.u[0], bb);
                    fma2(acc[1][j], X0.u[1], bb);
                    fma2(acc[2][j], X1.u[0], bb);
                    fma2(acc[3][j], X1.u[1], bb);
                }
            }
        }
    }
    __syncthreads();
    if (act) {
        #pragma unroll
        for (int i = 0; i < 4; i++) {
            int c = cb + 2 * i;
            float s0 = sc[c], s1 = sc[c + 1];
            #pragma unroll
            for (int j = 0; j < 5; j++) {
                float lo, hi; unpack2(acc[i][j], lo, hi);
                int q = qb + j;
                S[c * 50 + q]       = lo + s0 + sq[q];
                S[(c + 1) * 50 + q] = hi + s1 + sq[q];
            }
        }
    }
    __syncthreads();

    // ---------------- Phase 2: column (over c) softmax stats -----------------
    #pragma unroll 1
    for (int r = 0; r < 4; r++) {
        int q = w + 16 * r;
        if (q < LQ) {
            float m = -1e30f, s = 0.f;
            for (int c = lane; c < clen; c += 32) {
                float v = S[c * 50 + q];
                if (v > m) { s = s * __expf(m - v) + 1.f; m = v; }
                else       { s += __expf(v - m); }
            }
            #pragma unroll
            for (int o = 16; o; o >>= 1) {
                float m2 = __shfl_xor_sync(~0u, m, o);
                float s2 = __shfl_xor_sync(~0u, s, o);
                if (m2 > m) { s = s * __expf(m - m2) + s2; m = m2; }
                else        { s += s2 * __expf(m2 - m); }
            }
            if (!lane) { mxc[q] = m; invc[q] = 1.f / s; }
        }
    }
    __syncthreads();

    // ---------------- Phase 3: S_T out + A = S_T @ x_cont (regs) -------------
    {
        float* stb = A;   // 50*129 = 6450 <= 6600
        const int nq = (w < 2) ? 4 : 3;   // q = w + 16j
        ull accA[4][2];
        #pragma unroll
        for (int j = 0; j < 4; j++) { accA[j][0] = 0ull; accA[j][1] = 0ull; }
        float* ST_b = outST + (size_t)b * LQ * LC;

        #pragma unroll 1
        for (int c0 = 0; c0 < LC; c0 += 128) {
            const int CHN = (LC - c0 >= 128) ? 128 : 16;
            __syncthreads();
            if (CHN == 128) {
                for (int i = t; i < LQ * 128; i += 512) {
                    int q = i >> 7, cc = i & 127, c = c0 + cc;
                    float v = (c < clen) ? __expf(S[c * 50 + q] - mxc[q]) * invc[q] : 0.f;
                    stb[q * 129 + cc] = v;
                    ST_b[(size_t)q * LC + c] = v;
                }
            } else {
                for (int i = t; i < LQ * 16; i += 512) {
                    int q = i >> 4, cc = i & 15, c = c0 + cc;
                    float v = (c < clen) ? __expf(S[c * 50 + q] - mxc[q]) * invc[q] : 0.f;
                    stb[q * 129 + cc] = v;
                    ST_b[(size_t)q * LC + c] = v;
                }
            }
            __syncthreads();
            #pragma unroll 1
            for (int cc = 0; cc < CHN; cc += 4) {
                union { float4 f; ull u[2]; } X0, X1, X2, X3;
                X0.f = __ldg((const float4*)(xcb + (size_t)(c0 + cc) * DD) + lane);
                X1.f = __ldg((const float4*)(xcb + (size_t)(c0 + cc + 1) * DD) + lane);
                X2.f = __ldg((const float4*)(xcb + (size_t)(c0 + cc + 2) * DD) + lane);
                X3.f = __ldg((const float4*)(xcb + (size_t)(c0 + cc + 3) * DD) + lane);
                #pragma unroll
                for (int j = 0; j < 4; j++) {
                    if (j < nq) {
                        const float* sp = &stb[(w + 16 * j) * 129 + cc];
                        ull p0 = pack2(sp[0], sp[0]);
                        ull p1 = pack2(sp[1], sp[1]);
                        ull p2 = pack2(sp[2], sp[2]);
                        ull p3 = pack2(sp[3], sp[3]);
                        fma2(accA[j][0], X0.u[0], p0);
                        fma2(accA[j][1], X0.u[1], p0);
                        fma2(accA[j][0], X1.u[0], p1);
                        fma2(accA[j][1], X1.u[1], p1);
                        fma2(accA[j][0], X2.u[0], p2);
                        fma2(accA[j][1], X2.u[1], p2);
                        fma2(accA[j][0], X3.u[0], p3);
                        fma2(accA[j][1], X3.u[1], p3);
                    }
                }
            }
        }
        __syncthreads();   // stb dead; A region reusable
        #pragma unroll
        for (int j = 0; j < 4; j++) {
            if (j < nq) {
                union { float4 f; ull u[2]; } R;
                R.u[0] = accA[j][0]; R.u[1] = accA[j][1];
                *(float4*)&A[(w + 16 * j) * 132 + lane * 4] = R.f;
            }
        }
    }
    __syncthreads();

    // ---------------- Phase 4: row softmax -> S_bar in place -----------------
    #pragma unroll 1
    for (int r = 0; r < 25; r++) {
        int c = w + 16 * r;
        int q2 = lane + 32;
        float v1 = S[c * 50 + lane];
        float v2 = (q2 < LQ) ? S[c * 50 + q2] : 0.f;
        float m = (lane < qlen) ? v1 : -1e30f;
        if (q2 < LQ && q2 < qlen) m = fmaxf(m, v2);
        #pragma unroll
        for (int o = 16; o; o >>= 1) m = fmaxf(m, __shfl_xor_sync(~0u, m, o));
        float e1 = (lane < qlen) ? __expf(v1 - m) : 0.f;
        float e2 = (q2 < LQ && q2 < qlen) ? __expf(v2 - m) : 0.f;
        float s = e1 + e2;
        #pragma unroll
        for (int o = 16; o; o >>= 1) s += __shfl_xor_sync(~0u, s, o);
        float r1 = 1.f / s;
        e1 *= r1; e2 *= r1;
        S[c * 50 + lane] = e1;
        float* row = outSB + (size_t)(b * LC + c) * LQ;
        row[lane] = e1;
        if (q2 < LQ) { S[c * 50 + q2] = e2; row[q2] = e2; }
    }
    __syncthreads();

    // ---------------- Phase 5: c2q = Sbar@xq, q2c = Sbar@A, concat -----------
    #pragma unroll 1
    for (int pass = 0; pass < 7; pass++) {
        const int kmax = (pass < 6) ? 4 : 1;
        ull a1[4][2], a2[4][2];
        #pragma unroll
        for (int k = 0; k < 4; k++) {
            a1[k][0] = a1[k][1] = 0ull;
            a2[k][0] = a2[k][1] = 0ull;
        }
        const int cbase = pass * 64 + w;

        auto do_pair = [&](int q, const ull* XQ0u, const ull* XQ1u) {
            union { float4 f; ull u[2]; } AV0, AV1;
            AV0.f = *(const float4*)&A[q * 132 + lane * 4];
            AV1.f = *(const float4*)&A[(q + 1) * 132 + lane * 4];
            #pragma unroll
            for (int k = 0; k < 4; k++) {
                if (k < kmax) {
                    float2 sv = *(const float2*)&S[(cbase + 16 * k) * 50 + q];
                    ull s0 = pack2(sv.x, sv.x);
                    ull s1 = pack2(sv.y, sv.y);
                    fma2(a1[k][0], XQ0u[0], s0);
                    fma2(a1[k][1], XQ0u[1], s0);
                    fma2(a2[k][0], AV0.u[0], s0);
                    fma2(a2[k][1], AV0.u[1], s0);
                    fma2(a1[k][0], XQ1u[0], s1);
                    fma2(a1[k][1], XQ1u[1], s1);
                    fma2(a2[k][0], AV1.u[0], s1);
                    fma2(a2[k][1], AV1.u[1], s1);
                }
            }
        };

        #pragma unroll 1
        for (int q0 = 0; q0 < 48; q0 += 4) {
            union { float4 f; ull u[2]; } XQ0, XQ1, XQ2, XQ3;
            XQ0.f = __ldg((const float4*)(xqb + (size_t)q0 * DD) + lane);
            XQ1.f = __ldg((const float4*)(xqb + (size_t)(q0 + 1) * DD) + lane);
            XQ2.f = __ldg((const float4*)(xqb + (size_t)(q0 + 2) * DD) + lane);
            XQ3.f = __ldg((const float4*)(xqb + (size_t)(q0 + 3) * DD) + lane);
            do_pair(q0,     XQ0.u, XQ1.u);
            do_pair(q0 + 2, XQ2.u, XQ3.u);
        }
        {   // tail q = 48, 49
            union { float4 f; ull u[2]; } XQ0, XQ1;
            XQ0.f = __ldg((const float4*)(xqb + (size_t)48 * DD) + lane);
            XQ1.f = __ldg((const float4*)(xqb + (size_t)49 * DD) + lane);
            do_pair(48, XQ0.u, XQ1.u);
        }
        #pragma unroll
        for (int k = 0; k < 4; k++) {
            if (k < kmax) {
                int c = cbase + 16 * k;
                float4 xcv = __ldg((const float4*)(xcb + (size_t)c * DD) + lane);
                union { float4 f; ull u[2]; } C2Q, Q2C;
                C2Q.u[0] = a1[k][0]; C2Q.u[1] = a1[k][1];
                Q2C.u[0] = a2[k][0]; Q2C.u[1] = a2[k][1];
                float* base = out + ((size_t)b * LC + c) * (4 * DD) + lane * 4;
                *(float4*)(base)       = xcv;
                *(float4*)(base + 128) = C2Q.f;
                *(float4*)(base + 256) = make_float4(xcv.x * C2Q.f.x, xcv.y * C2Q.f.y,
                                                     xcv.z * C2Q.f.z, xcv.w * C2Q.f.w);
                *(float4*)(base + 384) = make_float4(xcv.x * Q2C.f.x, xcv.y * Q2C.f.y,
                                                     xcv.z * Q2C.f.z, xcv.w * Q2C.f.w);
            }
        }
    }
}

extern "C" void kernel_launch(void* const* d_in, const int* in_sizes, int n_in,
                              void* d_out, int out_size)
{
    const float* xc  = (const float*)d_in[0];
    const float* xq  = (const float*)d_in[1];
    const float* W0  = (const float*)d_in[2];
    const float* W1  = (const float*)d_in[3];
    const float* W2  = (const float*)d_in[4];
    const int* clen  = (const int*)d_in[5];
    const int* qlen  = (const int*)d_in[6];
    float* out = (float*)d_out;

    const size_t smem = (size_t)SM_TOT * sizeof(float);  // 108624 B
    cudaFuncSetAttribute(cqa4_kernel, cudaFuncAttributeMaxDynamicSharedMemorySize,
                         (int)smem);
    cqa4_kernel<<<NB, 512, smem>>>(xc, xq, W0, W1, W2, clen, qlen, out);
}